// round 2
// baseline (speedup 1.0000x reference)
#include <cuda_runtime.h>
#include <math.h>

// Problem dims (fixed by the dataset):
//   inputs: [G=8, E=8, C=512, H=1024] f32
//   wi:     [E, H, F=4096] f32, bi: [E, F]
//   wo:     [E, F, H] f32,      bo: [E, H]
//   out:    [G, E, C, H] f32
// Per expert e: X_e (M=G*C=4096 x H) @ wi_e (H x F) -> gelu -> @ wo_e (F x H)

namespace {
constexpr int G = 8;
constexpr int E = 8;
constexpr int C = 512;
constexpr int H = 1024;
constexpr int F = 4096;
constexpr int M = G * C;   // 4096 rows per expert (g-major, strided by expert)

constexpr int BM = 128;
constexpr int BN = 128;
constexpr int BK = 16;
constexpr int PAD = 4;     // smem inner-dim pad (keeps 16B alignment: 132*4 % 16 == 0)
}

// Intermediate activations [E][M][F] = 537 MB. Static __device__ scratch is the
// sanctioned no-alloc workaround (see pitfalls.md).
constexpr size_t SCRATCH_ELEMS = (size_t)E * (size_t)M * (size_t)F;
__device__ float g_scratch[SCRATCH_ELEMS];

__device__ __forceinline__ float gelu_exact(float x) {
    // keras/jax exact gelu: 0.5*x*(1+erf(x/sqrt(2)))
    return 0.5f * x * (1.0f + erff(x * 0.70710678118654752440f));
}

template <bool FIRST>
__global__ __launch_bounds__(256)
void ffn_gemm(const float* __restrict__ X,
              const float* __restrict__ W,
              const float* __restrict__ bias,
              float* __restrict__ Out)
{
    constexpr int KD = FIRST ? H : F;   // reduction dim
    constexpr int ND = FIRST ? F : H;   // output cols

    __shared__ float As[BK][BM + PAD];  // transposed A tile: As[k][m]
    __shared__ float Bs[BK][BN + PAD];  // Bs[k][n]

    const int tid = threadIdx.x;
    const int e   = blockIdx.z;
    const int m0  = blockIdx.y * BM;
    const int n0  = blockIdx.x * BN;

    // ---- A loader: each thread loads 8 consecutive k's of one row ----
    const int arow = tid >> 1;          // 0..127
    const int acol = (tid & 1) * 8;     // 0 or 8
    const int mrow = m0 + arow;
    const float* aptr;
    if (FIRST) {
        // inputs[g][e][c][h], g = mrow/512, c = mrow%512
        aptr = X + ((size_t)((mrow >> 9) * E + e) * C + (mrow & 511)) * H + acol;
    } else {
        aptr = g_scratch + ((size_t)e * M + mrow) * (size_t)F + acol;
    }

    // ---- B loader: 16 k-rows x 128 n-cols, fully coalesced ----
    const int brow = tid >> 4;          // 0..15
    const int bcol = (tid & 15) * 8;    // 0..120
    const float* bptr = W + (size_t)e * KD * (size_t)ND
                          + (size_t)brow * ND + n0 + bcol;

    // ---- compute mapping: 16x16 threads, 8x8 outputs each ----
    const int ty = tid >> 4;
    const int tx = tid & 15;

    float acc[8][8];
    #pragma unroll
    for (int i = 0; i < 8; i++)
        #pragma unroll
        for (int j = 0; j < 8; j++)
            acc[i][j] = 0.0f;

    for (int k0 = 0; k0 < KD; k0 += BK) {
        const float4 a0 = *(const float4*)(aptr + k0);
        const float4 a1 = *(const float4*)(aptr + k0 + 4);
        const float4 b0 = *(const float4*)(bptr + (size_t)k0 * ND);
        const float4 b1 = *(const float4*)(bptr + (size_t)k0 * ND + 4);

        __syncthreads();   // previous tile fully consumed before overwrite

        As[acol + 0][arow] = a0.x;
        As[acol + 1][arow] = a0.y;
        As[acol + 2][arow] = a0.z;
        As[acol + 3][arow] = a0.w;
        As[acol + 4][arow] = a1.x;
        As[acol + 5][arow] = a1.y;
        As[acol + 6][arow] = a1.z;
        As[acol + 7][arow] = a1.w;
        *(float4*)&Bs[brow][bcol]     = b0;
        *(float4*)&Bs[brow][bcol + 4] = b1;

        __syncthreads();

        #pragma unroll
        for (int k = 0; k < BK; k++) {
            float a[8], b[8];
            *(float4*)&a[0] = *(const float4*)&As[k][ty * 8];
            *(float4*)&a[4] = *(const float4*)&As[k][ty * 8 + 4];
            *(float4*)&b[0] = *(const float4*)&Bs[k][tx * 8];
            *(float4*)&b[4] = *(const float4*)&Bs[k][tx * 8 + 4];
            #pragma unroll
            for (int i = 0; i < 8; i++)
                #pragma unroll
                for (int j = 0; j < 8; j++)
                    acc[i][j] = fmaf(a[i], b[j], acc[i][j]);
        }
    }

    // ---- epilogue: +bias, (gelu), store ----
    float bv[8];
    const float* bexp = bias + (size_t)e * ND + n0 + tx * 8;
    #pragma unroll
    for (int j = 0; j < 8; j++) bv[j] = bexp[j];

    #pragma unroll
    for (int i = 0; i < 8; i++) {
        const int m = m0 + ty * 8 + i;
        float* orow;
        if (FIRST) {
            orow = g_scratch + ((size_t)e * M + m) * (size_t)F + n0 + tx * 8;
        } else {
            orow = Out + ((size_t)((m >> 9) * E + e) * C + (m & 511)) * H + n0 + tx * 8;
        }
        float t[8];
        #pragma unroll
        for (int j = 0; j < 8; j++) {
            float x = acc[i][j] + bv[j];
            t[j] = FIRST ? gelu_exact(x) : x;
        }
        *(float4*)&orow[0] = make_float4(t[0], t[1], t[2], t[3]);
        *(float4*)&orow[4] = make_float4(t[4], t[5], t[6], t[7]);
    }
}

extern "C" void kernel_launch(void* const* d_in, const int* in_sizes, int n_in,
                              void* d_out, int out_size)
{
    const float* inputs = (const float*)d_in[0];
    const float* wi     = (const float*)d_in[1];
    const float* bi     = (const float*)d_in[2];
    const float* wo     = (const float*)d_in[3];
    const float* bo     = (const float*)d_in[4];
    float* out          = (float*)d_out;

    dim3 blk(256);
    dim3 g1(F / BN, M / BM, E);   // (32, 32, 8)
    dim3 g2(H / BN, M / BM, E);   // ( 8, 32, 8)

    ffn_gemm<true ><<<g1, blk>>>(inputs, wi, bi, nullptr);
    ffn_gemm<false><<<g2, blk>>>(nullptr, wo, bo, out);
}